// round 5
// baseline (speedup 1.0000x reference)
#include <cuda_runtime.h>
#include <cuda_bf16.h>
#include <cstdint>

// HistogramLoss: fake/real [32,3,512,512] f32 -> scalar L1 of per-(B,C) 64-bin
// normalized histograms. Since every element falls in exactly one bin, the
// per-row normalizer is exactly HW, so we accumulate signed counts
// (+1 fake, -1 real) and compute sum|diff| / (HW * ROWS * BINS).

#define BINS 64
#define ROWS 96            // B*C = 32*3
#define HW   (512 * 512)   // 262144 elements per row
#define BLOCKS_PER_ROW 32
#define CHUNK (HW / BLOCKS_PER_ROW)   // 8192 elements
#define NWARPS 8
#define NTHREADS (NWARPS * 32)

// Signed count difference histogram (fake minus real). Zero-initialized at
// module load; the reduce kernel re-zeroes it after reading so every graph
// replay starts from zero.
__device__ int g_hist[ROWS * BINS];

__device__ __forceinline__ int bin_of(float x) {
    // clip((x - 0)/1, 0, 1) then idx = min(int(x*64), 63); x >= 0 so int() == floor
    x = __saturatef(x);
    int b = (int)(x * 64.0f);
    return b > 63 ? 63 : b;
}

__global__ __launch_bounds__(NTHREADS)
void hist_kernel(const float* __restrict__ fake, const float* __restrict__ real) {
    __shared__ int sh[NWARPS][BINS];   // per-warp privatized histograms

    const int tid  = threadIdx.x;
    const int warp = tid >> 5;

    // zero shared hists
    #pragma unroll
    for (int i = tid; i < NWARPS * BINS; i += NTHREADS)
        ((int*)sh)[i] = 0;
    __syncthreads();

    const int row   = blockIdx.y;
    const int chunk = blockIdx.x;
    const size_t base = (size_t)row * HW + (size_t)chunk * CHUNK;

    const float4* f4 = (const float4*)(fake + base);
    const float4* r4 = (const float4*)(real + base);
    const int n4 = CHUNK / 4;   // 2048 float4 per input

    int* myhist = sh[warp];

    #pragma unroll 4
    for (int i = tid; i < n4; i += NTHREADS) {
        float4 a = f4[i];
        atomicAdd(&myhist[bin_of(a.x)], 1);
        atomicAdd(&myhist[bin_of(a.y)], 1);
        atomicAdd(&myhist[bin_of(a.z)], 1);
        atomicAdd(&myhist[bin_of(a.w)], 1);
        float4 b = r4[i];
        atomicSub(&myhist[bin_of(b.x)], 1);
        atomicSub(&myhist[bin_of(b.y)], 1);
        atomicSub(&myhist[bin_of(b.z)], 1);
        atomicSub(&myhist[bin_of(b.w)], 1);
    }
    __syncthreads();

    // combine warp hists, one global atomic per (block, bin)
    for (int b = tid; b < BINS; b += NTHREADS) {
        int s = 0;
        #pragma unroll
        for (int w = 0; w < NWARPS; w++) s += sh[w][b];
        if (s != 0) atomicAdd(&g_hist[row * BINS + b], s);
    }
}

__global__ __launch_bounds__(256)
void reduce_kernel(float* __restrict__ out) {
    __shared__ float ssum[256];
    const int tid = threadIdx.x;

    float s = 0.0f;
    for (int i = tid; i < ROWS * BINS; i += 256) {
        int v = g_hist[i];
        g_hist[i] = 0;            // reset for next graph replay
        s += fabsf((float)v);
    }
    ssum[tid] = s;
    __syncthreads();

    #pragma unroll
    for (int stride = 128; stride > 0; stride >>= 1) {
        if (tid < stride) ssum[tid] += ssum[tid + stride];
        __syncthreads();
    }

    if (tid == 0) {
        // loss = (sum |cf - cr| / HW) / (ROWS * BINS)
        out[0] = ssum[0] * (1.0f / ((float)HW * (float)(ROWS * BINS)));
    }
}

extern "C" void kernel_launch(void* const* d_in, const int* in_sizes, int n_in,
                              void* d_out, int out_size) {
    const float* fake = (const float*)d_in[0];
    const float* real = (const float*)d_in[1];
    float* out = (float*)d_out;

    dim3 grid(BLOCKS_PER_ROW, ROWS);
    hist_kernel<<<grid, NTHREADS>>>(fake, real);
    reduce_kernel<<<1, 256>>>(out);
}

// round 10
// speedup vs baseline: 1.0101x; 1.0101x over previous
#include <cuda_runtime.h>
#include <cuda_bf16.h>
#include <cstdint>

// HistogramLoss: fake/real [32,3,512,512] f32 -> scalar L1 of per-(B,C) 64-bin
// normalized histograms. Every element lands in exactly one bin, so each row's
// normalizer is exactly HW; accumulate signed counts (+1 fake, -1 real) and
// loss = sum|diff| / (HW * ROWS * BINS).
//
// Single fused kernel: blocks accumulate into g_hist via one atomic per
// (block,bin); the LAST block (global ticket) reduces g_hist to the scalar and
// zeroes all state so CUDA-graph replays are deterministic.

#define BINS 64
#define ROWS 96            // B*C = 32*3
#define HW   (512 * 512)   // 262144 elements per row
#define BLOCKS_PER_ROW 32
#define CHUNK (HW / BLOCKS_PER_ROW)   // 8192 elements
#define NWARPS 8
#define NTHREADS (NWARPS * 32)
#define TOTAL_BLOCKS (BLOCKS_PER_ROW * ROWS)
#define NHIST (NWARPS * 2)            // two hists per warp (halves collisions)

// Signed count-difference histogram (fake minus real). Zero at module load;
// the last block re-zeroes it after reading so every replay starts from zero.
__device__ int g_hist[ROWS * BINS];
__device__ unsigned int g_ticket;     // zero-init; last block resets to 0

__device__ __forceinline__ int bin_of(float x) {
    // clip(x, 0, 1) then idx = min(int(x*64), 63); x >= 0 so int() == floor
    x = __saturatef(x);
    int b = (int)(x * 64.0f);
    return b > 63 ? 63 : b;
}

__global__ __launch_bounds__(NTHREADS)
void hist_loss_kernel(const float* __restrict__ fake,
                      const float* __restrict__ real,
                      float* __restrict__ out) {
    // Per-half-warp privatized histograms: each warp gets two 64-bin arrays;
    // lanes 0-15 use [2*warp], lanes 16-31 use [2*warp+1]. This halves the
    // same-address collision degree inside each shared-atomic instruction.
    __shared__ int sh[NHIST][BINS];
    __shared__ unsigned int s_ticket;

    const int tid  = threadIdx.x;
    const int warp = tid >> 5;
    const int half = (tid >> 4) & 1;

    #pragma unroll
    for (int i = tid; i < NHIST * BINS; i += NTHREADS)
        ((int*)sh)[i] = 0;
    __syncthreads();

    const int row   = blockIdx.y;
    const int chunk = blockIdx.x;
    const size_t base = (size_t)row * HW + (size_t)chunk * CHUNK;

    const float4* f4 = (const float4*)(fake + base);
    const float4* r4 = (const float4*)(real + base);
    const int n4 = CHUNK / 4;   // 2048 float4 per input

    int* myhist = sh[warp * 2 + half];

    #pragma unroll 4
    for (int i = tid; i < n4; i += NTHREADS) {
        float4 a = f4[i];
        atomicAdd(&myhist[bin_of(a.x)], 1);
        atomicAdd(&myhist[bin_of(a.y)], 1);
        atomicAdd(&myhist[bin_of(a.z)], 1);
        atomicAdd(&myhist[bin_of(a.w)], 1);
        float4 b = r4[i];
        atomicSub(&myhist[bin_of(b.x)], 1);
        atomicSub(&myhist[bin_of(b.y)], 1);
        atomicSub(&myhist[bin_of(b.z)], 1);
        atomicSub(&myhist[bin_of(b.w)], 1);
    }
    __syncthreads();

    // Combine privatized hists: one global atomic per (block, bin).
    for (int b = tid; b < BINS; b += NTHREADS) {
        int s = 0;
        #pragma unroll
        for (int h = 0; h < NHIST; h++) s += sh[h][b];
        if (s != 0) atomicAdd(&g_hist[row * BINS + b], s);
    }

    // ── last-block reduction ──────────────────────────────────────────────
    __threadfence();          // make our g_hist atomics visible before ticket
    __syncthreads();
    if (tid == 0)
        s_ticket = atomicAdd(&g_ticket, 1u);
    __syncthreads();
    if (s_ticket != TOTAL_BLOCKS - 1)
        return;

    // We are the last block: all g_hist updates are globally visible.
    __shared__ float ssum[NTHREADS];
    float s = 0.0f;
    #pragma unroll
    for (int i = tid; i < ROWS * BINS; i += NTHREADS) {
        int v = g_hist[i];
        g_hist[i] = 0;        // reset for next graph replay
        s += fabsf((float)v);
    }
    ssum[tid] = s;
    __syncthreads();

    #pragma unroll
    for (int stride = NTHREADS / 2; stride > 0; stride >>= 1) {
        if (tid < stride) ssum[tid] += ssum[tid + stride];
        __syncthreads();
    }

    if (tid == 0) {
        out[0] = ssum[0] * (1.0f / ((float)HW * (float)(ROWS * BINS)));
        g_ticket = 0;         // reset ticket for next graph replay
    }
}

extern "C" void kernel_launch(void* const* d_in, const int* in_sizes, int n_in,
                              void* d_out, int out_size) {
    const float* fake = (const float*)d_in[0];
    const float* real = (const float*)d_in[1];
    float* out = (float*)d_out;

    dim3 grid(BLOCKS_PER_ROW, ROWS);
    hist_loss_kernel<<<grid, NTHREADS>>>(fake, real, out);
}

// round 12
// speedup vs baseline: 1.0597x; 1.0491x over previous
#include <cuda_runtime.h>
#include <cuda_bf16.h>
#include <cstdint>

// HistogramLoss: fake/real [32,3,512,512] f32 -> scalar L1 of per-(B,C) 64-bin
// normalized histograms. Every element lands in exactly one bin, so each row's
// normalizer is exactly HW; accumulate signed counts (+1 fake, -1 real):
//   loss = sum|diff| / (HW * ROWS * BINS).
//
// Persistent single-wave kernel: grid = 148 SMs x 8 blocks, all co-resident
// (launch_bounds caps regs at 32). Each block processes an equal contiguous
// slice of the float4 index space (spans at most 2 rows), flushing its shared
// histogram at row boundaries. Last block (global ticket) reduces g_hist to
// the scalar and zeroes all state for deterministic CUDA-graph replay.

#define BINS 64
#define ROWS 96                   // B*C = 32*3
#define HW   (512 * 512)          // elements per row
#define N4_PER_ROW (HW / 4)       // 65536 float4 per row
#define N4_TOTAL (ROWS * N4_PER_ROW)  // 6,291,456 float4 per tensor
#define NWARPS 8
#define NTHREADS (NWARPS * 32)
#define NSM 148
#define BLOCKS_PER_SM 8
#define G_BLOCKS (NSM * BLOCKS_PER_SM)   // 1184 — exactly one wave
#define NHIST (NWARPS * 2)        // per-half-warp privatized hists

// Signed count-difference histogram (fake minus real). Zero at module load;
// the last block re-zeroes it after reading so every replay starts from zero.
__device__ int g_hist[ROWS * BINS];
__device__ unsigned int g_ticket;   // zero-init; last block resets to 0

__device__ __forceinline__ int bin_of(float x) {
    x = __saturatef(x);
    int b = (int)(x * 64.0f);
    return b > 63 ? 63 : b;
}

__global__ __launch_bounds__(NTHREADS, BLOCKS_PER_SM)
void hist_loss_kernel(const float* __restrict__ fake,
                      const float* __restrict__ real,
                      float* __restrict__ out) {
    __shared__ int sh[NHIST][BINS];
    __shared__ unsigned int s_ticket;

    const int tid  = threadIdx.x;
    const int warp = tid >> 5;
    const int half = (tid >> 4) & 1;
    int* myhist = sh[warp * 2 + half];

    #pragma unroll
    for (int i = tid; i < NHIST * BINS; i += NTHREADS)
        ((int*)sh)[i] = 0;
    __syncthreads();

    // Equal contiguous float4 ranges per block.
    const unsigned int lo = (unsigned int)(((uint64_t)blockIdx.x     * N4_TOTAL) / G_BLOCKS);
    const unsigned int hi = (unsigned int)(((uint64_t)(blockIdx.x+1) * N4_TOTAL) / G_BLOCKS);

    const float4* __restrict__ f4 = (const float4*)fake;
    const float4* __restrict__ r4 = (const float4*)real;

    const int row0 = (int)(lo >> 16);          // 65536 float4 per row
    const int row1 = (int)((hi - 1) >> 16);    // range spans at most 2 rows

    // Up to two passes (one per row touched).
    unsigned int seg_lo = lo;
    for (int row = row0; row <= row1; row++) {
        unsigned int seg_hi = (row == row1) ? hi : (unsigned int)(row + 1) << 16;

        #pragma unroll 4
        for (unsigned int i = seg_lo + tid; i < seg_hi; i += NTHREADS) {
            float4 a = __ldcs(f4 + i);
            atomicAdd(&myhist[bin_of(a.x)], 1);
            atomicAdd(&myhist[bin_of(a.y)], 1);
            atomicAdd(&myhist[bin_of(a.z)], 1);
            atomicAdd(&myhist[bin_of(a.w)], 1);
            float4 b = __ldcs(r4 + i);
            atomicSub(&myhist[bin_of(b.x)], 1);
            atomicSub(&myhist[bin_of(b.y)], 1);
            atomicSub(&myhist[bin_of(b.z)], 1);
            atomicSub(&myhist[bin_of(b.w)], 1);
        }

        // Flush shared hist for this row into the global hist.
        __syncthreads();
        for (int b = tid; b < BINS; b += NTHREADS) {
            int s = 0;
            #pragma unroll
            for (int h = 0; h < NHIST; h++) s += sh[h][b];
            if (s != 0) atomicAdd(&g_hist[row * BINS + b], s);
        }
        if (row != row1) {
            // Re-zero for the next row's pass (barrier both sides: combine
            // reads must finish before zeroing; zeroing before next accum).
            __syncthreads();
            #pragma unroll
            for (int i = tid; i < NHIST * BINS; i += NTHREADS)
                ((int*)sh)[i] = 0;
            __syncthreads();
        }
        seg_lo = seg_hi;
    }

    // ── last-block reduction ──────────────────────────────────────────────
    __threadfence();
    __syncthreads();
    if (tid == 0)
        s_ticket = atomicAdd(&g_ticket, 1u);
    __syncthreads();
    if (s_ticket != G_BLOCKS - 1)
        return;

    __shared__ float ssum[NTHREADS];
    float s = 0.0f;
    #pragma unroll
    for (int i = tid; i < ROWS * BINS; i += NTHREADS) {
        int v = g_hist[i];
        g_hist[i] = 0;          // reset for next graph replay
        s += fabsf((float)v);
    }
    ssum[tid] = s;
    __syncthreads();

    #pragma unroll
    for (int stride = NTHREADS / 2; stride > 0; stride >>= 1) {
        if (tid < stride) ssum[tid] += ssum[tid + stride];
        __syncthreads();
    }

    if (tid == 0) {
        out[0] = ssum[0] * (1.0f / ((float)HW * (float)(ROWS * BINS)));
        g_ticket = 0;           // reset ticket for next graph replay
    }
}

extern "C" void kernel_launch(void* const* d_in, const int* in_sizes, int n_in,
                              void* d_out, int out_size) {
    const float* fake = (const float*)d_in[0];
    const float* real = (const float*)d_in[1];
    float* out = (float*)d_out;

    hist_loss_kernel<<<G_BLOCKS, NTHREADS>>>(fake, real, out);
}